// round 14
// baseline (speedup 1.0000x reference)
#include <cuda_runtime.h>

#define N_CELLS 50000
#define HID 64
#define DEG 16
#define KND 4

// ---- scratch (device globals; no allocations allowed) ----
__device__ float g_cent[N_CELLS * 3];        // cell centroids
__device__ float g_P[(size_t)N_CELLS * 128]; // [A = F@W1a + b1 | G = F@W1b]
__device__ float g_hsum[(size_t)N_CELLS * HID]; // sum_j silu(pre_j)
__device__ float g_sS[(size_t)N_CELLS * HID];   // silu(S_pre)
__device__ float g_W2u[HID * HID];           // (W2/16) @ Wu1[64:128]
__device__ float g_bc[HID];                  // bu1 + b2 @ Wu1[64:128]

static __device__ __forceinline__ float silu_f(float x) {
    // silu(x) = x*sigmoid(x) = xh + xh*tanh(xh), xh = x/2   (1 MUFU)
    float t, xh = 0.5f * x;
    asm("tanh.approx.f32 %0, %1;" : "=f"(t) : "f"(xh));
    return fmaf(xh, t, xh);
}
static __device__ __forceinline__ float sqrt_approx(float x) {
    float r;
    asm("sqrt.approx.f32 %0, %1;" : "=f"(r) : "f"(x));
    return r;
}

// ---- combine weights: W2u = (W2 @ Wu1b)/16 ; bc = bu1 + b2 @ Wu1b ----
__global__ void k_combine(const float* __restrict__ W2, const float* __restrict__ b2,
                          const float* __restrict__ Wu1, const float* __restrict__ bu1) {
    int k = threadIdx.x;  // 0..63
    int r = blockIdx.x;   // 0..63 weight rows, 64 => bias
    if (r < HID) {
        float acc = 0.f;
        #pragma unroll 8
        for (int m = 0; m < HID; m++)
            acc = fmaf(W2[r * HID + m], Wu1[(HID + m) * HID + k], acc);
        g_W2u[r * HID + k] = acc * (1.0f / 16.0f);
    } else {
        float acc = bu1[k];
        for (int m = 0; m < HID; m++)
            acc = fmaf(b2[m], Wu1[(HID + m) * HID + k], acc);
        g_bc[k] = acc;
    }
}

// ---- centroids: cent[i] = mean of positions[4i..4i+4) ----
__global__ void k_cent(const float* __restrict__ pos) {
    int i = blockIdx.x * blockDim.x + threadIdx.x;
    if (i >= N_CELLS) return;
    const float4* p = (const float4*)(pos + (size_t)i * 12);
    float4 v0 = p[0], v1 = p[1], v2 = p[2];
    g_cent[3 * i + 0] = 0.25f * (v0.x + v0.w + v1.z + v2.y);
    g_cent[3 * i + 1] = 0.25f * (v0.y + v1.x + v1.w + v2.z);
    g_cent[3 * i + 2] = 0.25f * (v0.z + v1.y + v2.x + v2.w);
}

// ---- P[N,128] = F @ [W1a | W1b] (+ b1 on first 64 cols) ----
// column-owner: thread k holds its 64-entry weight column in registers,
// features broadcast from smem.
__global__ __launch_bounds__(128) void k_pre(const float* __restrict__ F,
                                             const float* __restrict__ W1,
                                             const float* __restrict__ b1) {
    __shared__ float fs[32 * 64];
    int k = threadIdx.x;
    float w[64];
    float bias;
    if (k < 64) {
        #pragma unroll
        for (int r = 0; r < 64; r++) w[r] = W1[r * 64 + k];
        bias = b1[k];
    } else {
        #pragma unroll
        for (int r = 0; r < 64; r++) w[r] = W1[(64 + r) * 64 + (k - 64)];
        bias = 0.f;
    }
    int c0 = blockIdx.x * 32;
    int nc = min(32, N_CELLS - c0);
    const float4* src = (const float4*)(F + (size_t)c0 * 64);
    float4* dst = (float4*)fs;
    for (int t = threadIdx.x; t < nc * 16; t += 128) dst[t] = src[t];
    __syncthreads();
    for (int c = 0; c < nc; c++) {
        float a0 = bias, a1 = 0.f;
        #pragma unroll
        for (int r = 0; r < 64; r += 2) {
            a0 = fmaf(fs[c * 64 + r],     w[r],     a0);
            a1 = fmaf(fs[c * 64 + r + 1], w[r + 1], a1);
        }
        g_P[(size_t)(c0 + c) * 128 + k] = a0 + a1;
    }
}

// ---- pair phase: hsum[i] = sum_d silu(A_i + G_j + geom_ij * W1[128]) ----
// one warp per cell, each lane owns 2 hidden dims (float2)
__global__ __launch_bounds__(256) void k_pair(const int* __restrict__ nbr,
                                              const float* __restrict__ W1) {
    int gw = (blockIdx.x * 256 + threadIdx.x) >> 5;
    int lane = threadIdx.x & 31;
    if (gw >= N_CELLS) return;
    int i = gw;
    float2 a = *(const float2*)&g_P[(size_t)i * 128 + 2 * lane];
    float2 w = *(const float2*)&W1[128 * 64 + 2 * lane];
    float cix = g_cent[3 * i], ciy = g_cent[3 * i + 1], ciz = g_cent[3 * i + 2];
    const int4* nb = (const int4*)(nbr + (size_t)i * 16);
    int4 n0 = nb[0], n1 = nb[1], n2 = nb[2], n3 = nb[3];
    int js[16] = {n0.x, n0.y, n0.z, n0.w, n1.x, n1.y, n1.z, n1.w,
                  n2.x, n2.y, n2.z, n2.w, n3.x, n3.y, n3.z, n3.w};
    float hx = 0.f, hy = 0.f;
    #pragma unroll
    for (int d = 0; d < 16; d++) {
        int j = js[d];
        float dx = cix - g_cent[3 * j];
        float dy = ciy - g_cent[3 * j + 1];
        float dz = ciz - g_cent[3 * j + 2];
        float geom = sqrt_approx(fmaf(dx, dx, fmaf(dy, dy, dz * dz)));
        float2 g = *(const float2*)&g_P[(size_t)j * 128 + 64 + 2 * lane];
        float p0 = fmaf(geom, w.x, a.x + g.x);
        float p1 = fmaf(geom, w.y, a.y + g.y);
        hx += silu_f(p0);
        hy += silu_f(p1);
    }
    *(float2*)&g_hsum[(size_t)i * 64 + 2 * lane] = make_float2(hx, hy);
}

// ---- update stage 1: sS = silu(F@Wu1a + hsum@W2u + bc) ----
__global__ __launch_bounds__(64) void k_upd1(const float* __restrict__ F,
                                             const float* __restrict__ Wu1) {
    __shared__ float fs[32 * 64];
    __shared__ float hs[32 * 64];
    int k = threadIdx.x;
    float wa[64], wb[64];
    #pragma unroll
    for (int r = 0; r < 64; r++) {
        wa[r] = Wu1[r * 64 + k];
        wb[r] = g_W2u[r * 64 + k];
    }
    float bias = g_bc[k];
    int c0 = blockIdx.x * 32;
    int nc = min(32, N_CELLS - c0);
    {
        const float4* s1 = (const float4*)(F + (size_t)c0 * 64);
        const float4* s2 = (const float4*)(g_hsum + (size_t)c0 * 64);
        float4* d1 = (float4*)fs;
        float4* d2 = (float4*)hs;
        for (int t = threadIdx.x; t < nc * 16; t += 64) {
            d1[t] = s1[t];
            d2[t] = s2[t];
        }
    }
    __syncthreads();
    for (int c = 0; c < nc; c++) {
        float a0 = bias, a1 = 0.f;
        #pragma unroll
        for (int r = 0; r < 64; r += 2) {
            a0 = fmaf(fs[c * 64 + r],     wa[r],     a0);
            a1 = fmaf(fs[c * 64 + r + 1], wa[r + 1], a1);
            a0 = fmaf(hs[c * 64 + r],     wb[r],     a0);
            a1 = fmaf(hs[c * 64 + r + 1], wb[r + 1], a1);
        }
        g_sS[(size_t)(c0 + c) * 64 + k] = silu_f(a0 + a1);
    }
}

// ---- update stage 2: out = F + sS@Wu2 + bu2 ----
__global__ __launch_bounds__(64) void k_upd2(const float* __restrict__ F,
                                             const float* __restrict__ Wu2,
                                             const float* __restrict__ bu2,
                                             float* __restrict__ out) {
    __shared__ float ss[32 * 64];
    int k = threadIdx.x;
    float w[64];
    #pragma unroll
    for (int r = 0; r < 64; r++) w[r] = Wu2[r * 64 + k];
    float bias = bu2[k];
    int c0 = blockIdx.x * 32;
    int nc = min(32, N_CELLS - c0);
    const float4* s1 = (const float4*)(g_sS + (size_t)c0 * 64);
    float4* d1 = (float4*)ss;
    for (int t = threadIdx.x; t < nc * 16; t += 64) d1[t] = s1[t];
    __syncthreads();
    for (int c = 0; c < nc; c++) {
        float a0 = bias, a1 = 0.f;
        #pragma unroll
        for (int r = 0; r < 64; r += 2) {
            a0 = fmaf(ss[c * 64 + r],     w[r],     a0);
            a1 = fmaf(ss[c * 64 + r + 1], w[r + 1], a1);
        }
        size_t idx = (size_t)(c0 + c) * 64 + k;
        out[idx] = F[idx] + a0 + a1;
    }
}

extern "C" void kernel_launch(void* const* d_in, const int* in_sizes, int n_in,
                              void* d_out, int out_size) {
    const float* F   = (const float*)d_in[0];
    const float* pos = (const float*)d_in[1];
    const int*   nbr = (const int*)d_in[2];
    const float* W1  = (const float*)d_in[3];
    const float* b1  = (const float*)d_in[4];
    const float* W2  = (const float*)d_in[5];
    const float* b2  = (const float*)d_in[6];
    const float* Wu1 = (const float*)d_in[7];
    const float* bu1 = (const float*)d_in[8];
    const float* Wu2 = (const float*)d_in[9];
    const float* bu2 = (const float*)d_in[10];
    float* out = (float*)d_out;

    k_combine<<<65, 64>>>(W2, b2, Wu1, bu1);
    k_cent<<<(N_CELLS + 255) / 256, 256>>>(pos);
    k_pre<<<(N_CELLS + 31) / 32, 128>>>(F, W1, b1);
    k_pair<<<(N_CELLS * 32 + 255) / 256, 256>>>(nbr, W1);
    k_upd1<<<(N_CELLS + 31) / 32, 64>>>(F, Wu1);
    k_upd2<<<(N_CELLS + 31) / 32, 64>>>(F, Wu2, bu2, out);

    // second output: positions passthrough
    long long nh = (long long)N_CELLS * HID;
    long long np = (long long)N_CELLS * KND * 3;
    if ((long long)out_size >= nh + np) {
        cudaMemcpyAsync(out + nh, pos, (size_t)np * sizeof(float),
                        cudaMemcpyDeviceToDevice, 0);
    }
}

// round 15
// speedup vs baseline: 1.1090x; 1.1090x over previous
#include <cuda_runtime.h>

#define N_CELLS 50000
#define HID 64
#define DEG 16
#define KND 4

typedef unsigned long long u64;

// ---- scratch (device globals; no allocations allowed) ----
__device__ float g_cent[N_CELLS * 3];           // cell centroids
__device__ float g_P[(size_t)N_CELLS * 128];    // [A = F@W1a + b1 | G = F@W1b]
__device__ float g_hsum[(size_t)N_CELLS * HID]; // sum_j silu(pre_j)
__device__ float g_sS[(size_t)N_CELLS * HID];   // silu(S_pre)
__device__ float g_W2u[HID * HID];              // (W2/16) @ Wu1[64:128]
__device__ float g_bc[HID];                     // bu1 + b2 @ Wu1[64:128]

// ---- packed f32x2 helpers (Blackwell FFMA2 path) ----
static __device__ __forceinline__ u64 pk2(float lo, float hi) {
    u64 r; asm("mov.b64 %0, {%1, %2};" : "=l"(r) : "f"(lo), "f"(hi)); return r;
}
static __device__ __forceinline__ void upk2(u64 v, float& lo, float& hi) {
    asm("mov.b64 {%0, %1}, %2;" : "=f"(lo), "=f"(hi) : "l"(v));
}
static __device__ __forceinline__ u64 fma2(u64 a, u64 b, u64 c) {
    u64 d; asm("fma.rn.f32x2 %0, %1, %2, %3;" : "=l"(d) : "l"(a), "l"(b), "l"(c)); return d;
}
static __device__ __forceinline__ u64 add2(u64 a, u64 b) {
    u64 d; asm("add.rn.f32x2 %0, %1, %2;" : "=l"(d) : "l"(a), "l"(b)); return d;
}
static __device__ __forceinline__ u64 mul2(u64 a, u64 b) {
    u64 d; asm("mul.rn.f32x2 %0, %1, %2;" : "=l"(d) : "l"(a), "l"(b)); return d;
}

static __device__ __forceinline__ float tanh_ap(float x) {
    float t; asm("tanh.approx.f32 %0, %1;" : "=f"(t) : "f"(x)); return t;
}
static __device__ __forceinline__ float sqrt_approx(float x) {
    float r; asm("sqrt.approx.f32 %0, %1;" : "=f"(r) : "f"(x)); return r;
}

// ---- combine weights: W2u = (W2 @ Wu1b)/16 ; bc = bu1 + b2 @ Wu1b ----
__global__ void k_combine(const float* __restrict__ W2, const float* __restrict__ b2,
                          const float* __restrict__ Wu1, const float* __restrict__ bu1) {
    int k = threadIdx.x;  // 0..63
    int r = blockIdx.x;   // 0..63 weight rows, 64 => bias
    if (r < HID) {
        float acc = 0.f;
        #pragma unroll 8
        for (int m = 0; m < HID; m++)
            acc = fmaf(W2[r * HID + m], Wu1[(HID + m) * HID + k], acc);
        g_W2u[r * HID + k] = acc * (1.0f / 16.0f);
    } else {
        float acc = bu1[k];
        for (int m = 0; m < HID; m++)
            acc = fmaf(b2[m], Wu1[(HID + m) * HID + k], acc);
        g_bc[k] = acc;
    }
}

// ---- centroids ----
__global__ void k_cent(const float* __restrict__ pos) {
    int i = blockIdx.x * blockDim.x + threadIdx.x;
    if (i >= N_CELLS) return;
    const float4* p = (const float4*)(pos + (size_t)i * 12);
    float4 v0 = p[0], v1 = p[1], v2 = p[2];
    g_cent[3 * i + 0] = 0.25f * (v0.x + v0.w + v1.z + v2.y);
    g_cent[3 * i + 1] = 0.25f * (v0.y + v1.x + v1.w + v2.z);
    g_cent[3 * i + 2] = 0.25f * (v0.z + v1.y + v2.x + v2.w);
}

// ---- P[N,128] = F @ [W1a | W1b] (+ b1 on first 64 cols) ----
// column-owner, packed f32x2: 16 LDS.128 + 32 FFMA2 per cell per thread
__global__ __launch_bounds__(128) void k_pre(const float* __restrict__ F,
                                             const float* __restrict__ W1,
                                             const float* __restrict__ b1) {
    __shared__ __align__(16) float fs[32 * 64];
    int k = threadIdx.x;
    const float* wcol;
    float bias;
    if (k < 64) { wcol = W1 + k; bias = b1[k]; }
    else        { wcol = W1 + 64 * 64 + (k - 64); bias = 0.f; }
    u64 wp[32];
    #pragma unroll
    for (int r = 0; r < 32; r++)
        wp[r] = pk2(wcol[(2 * r) * 64], wcol[(2 * r + 1) * 64]);

    int c0 = blockIdx.x * 32;
    int nc = min(32, N_CELLS - c0);
    {
        const float4* src = (const float4*)(F + (size_t)c0 * 64);
        float4* dst = (float4*)fs;
        for (int t = threadIdx.x; t < nc * 16; t += 128) dst[t] = src[t];
    }
    __syncthreads();
    for (int c = 0; c < nc; c++) {
        u64 a0 = pk2(bias, 0.f), a1 = 0ull;
        const ulonglong2* fp = (const ulonglong2*)&fs[c * 64];
        #pragma unroll
        for (int r = 0; r < 16; r++) {
            ulonglong2 q = fp[r];
            a0 = fma2(q.x, wp[2 * r],     a0);
            a1 = fma2(q.y, wp[2 * r + 1], a1);
        }
        float l0, h0, l1, h1; upk2(a0, l0, h0); upk2(a1, l1, h1);
        g_P[(size_t)(c0 + c) * 128 + k] = (l0 + h0) + (l1 + h1);
    }
}

// ---- pair phase: hsum[i] = sum_d silu(A_i + G_j + geom_ij * w) ----
// one warp per cell; lanes 0-15 precompute geom; main loop fully packed
__global__ __launch_bounds__(256) void k_pair(const int* __restrict__ nbr,
                                              const float* __restrict__ W1) {
    const unsigned FULL = 0xFFFFFFFFu;
    int gw = (blockIdx.x * 256 + threadIdx.x) >> 5;  // cell (exactly 50000 warps)
    int lane = threadIdx.x & 31;
    int i = gw;
    u64 a = *(const u64*)&g_P[(size_t)i * 128 + 2 * lane];
    u64 w = *(const u64*)&W1[128 * 64 + 2 * lane];
    const u64 half2c = pk2(0.5f, 0.5f);
    const float* pbase = g_P + 64 + 2 * lane;

    // per-lane neighbor + geometry (lanes 16-31 mirror 0-15)
    int jd = __ldg(&nbr[(size_t)i * 16 + (lane & 15)]);
    float cix = g_cent[3 * i], ciy = g_cent[3 * i + 1], ciz = g_cent[3 * i + 2];
    float dx = cix - g_cent[3 * jd];
    float dy = ciy - g_cent[3 * jd + 1];
    float dz = ciz - g_cent[3 * jd + 2];
    float geomv = sqrt_approx(fmaf(dx, dx, fmaf(dy, dy, dz * dz)));

    u64 acc = 0ull;
    #pragma unroll
    for (int d = 0; d < 16; d++) {
        int j = __shfl_sync(FULL, jd, d);
        float geom = __shfl_sync(FULL, geomv, d);
        u64 g = *(const u64*)(pbase + (size_t)j * 128);
        u64 pre = fma2(pk2(geom, geom), w, add2(a, g));
        u64 xh = mul2(pre, half2c);
        float xl, xr; upk2(xh, xl, xr);
        u64 t = pk2(tanh_ap(xl), tanh_ap(xr));
        acc = add2(acc, fma2(xh, t, xh));
    }
    *(u64*)&g_hsum[(size_t)i * 64 + 2 * lane] = acc;
}

// ---- update stage 1: sS = silu(F@Wu1a + hsum@W2u + bc), packed ----
__global__ __launch_bounds__(64) void k_upd1(const float* __restrict__ F,
                                             const float* __restrict__ Wu1) {
    __shared__ __align__(16) float fs[32 * 64];
    __shared__ __align__(16) float hs[32 * 64];
    int k = threadIdx.x;
    u64 wa[32], wb[32];
    #pragma unroll
    for (int r = 0; r < 32; r++) {
        wa[r] = pk2(Wu1[(2 * r) * 64 + k],  Wu1[(2 * r + 1) * 64 + k]);
        wb[r] = pk2(g_W2u[(2 * r) * 64 + k], g_W2u[(2 * r + 1) * 64 + k]);
    }
    float bias = g_bc[k];
    int c0 = blockIdx.x * 32;
    int nc = min(32, N_CELLS - c0);
    {
        const float4* s1 = (const float4*)(F + (size_t)c0 * 64);
        const float4* s2 = (const float4*)(g_hsum + (size_t)c0 * 64);
        float4* d1 = (float4*)fs;
        float4* d2 = (float4*)hs;
        for (int t = threadIdx.x; t < nc * 16; t += 64) { d1[t] = s1[t]; d2[t] = s2[t]; }
    }
    __syncthreads();
    for (int c = 0; c < nc; c++) {
        u64 a0 = pk2(bias, 0.f), a1 = 0ull;
        const ulonglong2* fp = (const ulonglong2*)&fs[c * 64];
        const ulonglong2* hp = (const ulonglong2*)&hs[c * 64];
        #pragma unroll
        for (int r = 0; r < 16; r++) {
            ulonglong2 qf = fp[r], qh = hp[r];
            a0 = fma2(qf.x, wa[2 * r],     a0);
            a1 = fma2(qf.y, wa[2 * r + 1], a1);
            a0 = fma2(qh.x, wb[2 * r],     a0);
            a1 = fma2(qh.y, wb[2 * r + 1], a1);
        }
        float l0, h0, l1, h1; upk2(a0, l0, h0); upk2(a1, l1, h1);
        float x = (l0 + h0) + (l1 + h1);
        float xh = 0.5f * x;
        g_sS[(size_t)(c0 + c) * 64 + k] = fmaf(xh, tanh_ap(xh), xh);
    }
}

// ---- update stage 2: out = F + sS@Wu2 + bu2, packed ----
__global__ __launch_bounds__(64) void k_upd2(const float* __restrict__ F,
                                             const float* __restrict__ Wu2,
                                             const float* __restrict__ bu2,
                                             float* __restrict__ out) {
    __shared__ __align__(16) float ss[32 * 64];
    int k = threadIdx.x;
    u64 wp[32];
    #pragma unroll
    for (int r = 0; r < 32; r++)
        wp[r] = pk2(Wu2[(2 * r) * 64 + k], Wu2[(2 * r + 1) * 64 + k]);
    float bias = bu2[k];
    int c0 = blockIdx.x * 32;
    int nc = min(32, N_CELLS - c0);
    {
        const float4* s1 = (const float4*)(g_sS + (size_t)c0 * 64);
        float4* d1 = (float4*)ss;
        for (int t = threadIdx.x; t < nc * 16; t += 64) d1[t] = s1[t];
    }
    __syncthreads();
    for (int c = 0; c < nc; c++) {
        u64 a0 = pk2(bias, 0.f), a1 = 0ull;
        const ulonglong2* sp = (const ulonglong2*)&ss[c * 64];
        #pragma unroll
        for (int r = 0; r < 16; r++) {
            ulonglong2 q = sp[r];
            a0 = fma2(q.x, wp[2 * r],     a0);
            a1 = fma2(q.y, wp[2 * r + 1], a1);
        }
        float l0, h0, l1, h1; upk2(a0, l0, h0); upk2(a1, l1, h1);
        size_t idx = (size_t)(c0 + c) * 64 + k;
        out[idx] = F[idx] + (l0 + h0) + (l1 + h1);
    }
}

extern "C" void kernel_launch(void* const* d_in, const int* in_sizes, int n_in,
                              void* d_out, int out_size) {
    const float* F   = (const float*)d_in[0];
    const float* pos = (const float*)d_in[1];
    const int*   nbr = (const int*)d_in[2];
    const float* W1  = (const float*)d_in[3];
    const float* b1  = (const float*)d_in[4];
    const float* W2  = (const float*)d_in[5];
    const float* b2  = (const float*)d_in[6];
    const float* Wu1 = (const float*)d_in[7];
    const float* bu1 = (const float*)d_in[8];
    const float* Wu2 = (const float*)d_in[9];
    const float* bu2 = (const float*)d_in[10];
    float* out = (float*)d_out;

    k_combine<<<65, 64>>>(W2, b2, Wu1, bu1);
    k_cent<<<(N_CELLS + 255) / 256, 256>>>(pos);
    k_pre<<<(N_CELLS + 31) / 32, 128>>>(F, W1, b1);
    k_pair<<<(N_CELLS * 32 + 255) / 256, 256>>>(nbr, W1);
    k_upd1<<<(N_CELLS + 31) / 32, 64>>>(F, Wu1);
    k_upd2<<<(N_CELLS + 31) / 32, 64>>>(F, Wu2, bu2, out);

    // second output: positions passthrough
    long long nh = (long long)N_CELLS * HID;
    long long np = (long long)N_CELLS * KND * 3;
    if ((long long)out_size >= nh + np) {
        cudaMemcpyAsync(out + nh, pos, (size_t)np * sizeof(float),
                        cudaMemcpyDeviceToDevice, 0);
    }
}

// round 16
// speedup vs baseline: 1.1490x; 1.0360x over previous
#include <cuda_runtime.h>

#define N_CELLS 50000
#define HID 64
#define DEG 16
#define KND 4
#define NTILES 1563           // ceil(50000/32)
#define PRE_BLKS 592
#define CENT_BLKS 391         // 50000/128
#define CMB_BLKS 65
#define POS_BLKS 1172         // 150000 float4 / 128
#define UPD_BLKS 740

typedef unsigned long long u64;

// ---- scratch (device globals; no allocations allowed) ----
__device__ float4 g_cent4[N_CELLS];             // padded centroids (w unused)
__device__ float g_P[(size_t)N_CELLS * 128];    // [A = F@W1a + b1 | G = F@W1b]
__device__ float g_hsum[(size_t)N_CELLS * HID]; // sum_j silu(pre_j)
__device__ float g_W2u[HID * HID];              // (W2/16) @ Wu1[64:128]
__device__ float g_bc[HID];                     // bu1 + b2 @ Wu1[64:128]

// ---- packed f32x2 helpers ----
static __device__ __forceinline__ u64 pk2(float lo, float hi) {
    u64 r; asm("mov.b64 %0, {%1, %2};" : "=l"(r) : "f"(lo), "f"(hi)); return r;
}
static __device__ __forceinline__ void upk2(u64 v, float& lo, float& hi) {
    asm("mov.b64 {%0, %1}, %2;" : "=f"(lo), "=f"(hi) : "l"(v));
}
static __device__ __forceinline__ u64 fma2(u64 a, u64 b, u64 c) {
    u64 d; asm("fma.rn.f32x2 %0, %1, %2, %3;" : "=l"(d) : "l"(a), "l"(b), "l"(c)); return d;
}
static __device__ __forceinline__ u64 add2(u64 a, u64 b) {
    u64 d; asm("add.rn.f32x2 %0, %1, %2;" : "=l"(d) : "l"(a), "l"(b)); return d;
}
static __device__ __forceinline__ u64 mul2(u64 a, u64 b) {
    u64 d; asm("mul.rn.f32x2 %0, %1, %2;" : "=l"(d) : "l"(a), "l"(b)); return d;
}
static __device__ __forceinline__ float tanh_ap(float x) {
    float t; asm("tanh.approx.f32 %0, %1;" : "=f"(t) : "f"(x)); return t;
}
static __device__ __forceinline__ float sqrt_approx(float x) {
    float r; asm("sqrt.approx.f32 %0, %1;" : "=f"(r) : "f"(x)); return r;
}

// ============================================================
// K1: multi-role mega-kernel (128 threads/block)
//   blocks [0, PRE_BLKS):                 P = F @ [W1a|W1b] (+b1), persistent
//   next CENT_BLKS:                       centroids -> float4
//   next CMB_BLKS:                        W2u / bc combine
//   next POS_BLKS:                        positions passthrough copy
// ============================================================
__global__ __launch_bounds__(128) void k_mega(
    const float* __restrict__ F, const float* __restrict__ W1,
    const float* __restrict__ b1, const float* __restrict__ pos,
    const float* __restrict__ W2, const float* __restrict__ b2,
    const float* __restrict__ Wu1, const float* __restrict__ bu1,
    float* __restrict__ out)
{
    int blk = blockIdx.x;
    if (blk < PRE_BLKS) {
        // ---- P precompute (column-owner, packed, persistent) ----
        __shared__ __align__(16) float fs[32 * 64];
        int k = threadIdx.x;
        const float* wcol;
        float bias;
        if (k < 64) { wcol = W1 + k; bias = b1[k]; }
        else        { wcol = W1 + 64 * 64 + (k - 64); bias = 0.f; }
        u64 wp[32];
        #pragma unroll
        for (int r = 0; r < 32; r++)
            wp[r] = pk2(wcol[(2 * r) * 64], wcol[(2 * r + 1) * 64]);

        for (int t = blk; t < NTILES; t += PRE_BLKS) {
            int c0 = t * 32;
            int nc = min(32, N_CELLS - c0);
            {
                const float4* src = (const float4*)(F + (size_t)c0 * 64);
                float4* dst = (float4*)fs;
                for (int q = threadIdx.x; q < nc * 16; q += 128) dst[q] = src[q];
            }
            __syncthreads();
            for (int c = 0; c < nc; c++) {
                u64 a0 = pk2(bias, 0.f), a1 = 0ull;
                const ulonglong2* fp = (const ulonglong2*)&fs[c * 64];
                #pragma unroll
                for (int r = 0; r < 16; r++) {
                    ulonglong2 q = fp[r];
                    a0 = fma2(q.x, wp[2 * r],     a0);
                    a1 = fma2(q.y, wp[2 * r + 1], a1);
                }
                float l0, h0, l1, h1; upk2(a0, l0, h0); upk2(a1, l1, h1);
                g_P[(size_t)(c0 + c) * 128 + k] = (l0 + h0) + (l1 + h1);
            }
            __syncthreads();
        }
    } else if (blk < PRE_BLKS + CENT_BLKS) {
        // ---- centroids ----
        int i = (blk - PRE_BLKS) * 128 + threadIdx.x;
        if (i < N_CELLS) {
            const float4* p = (const float4*)(pos + (size_t)i * 12);
            float4 v0 = p[0], v1 = p[1], v2 = p[2];
            float4 c;
            c.x = 0.25f * (v0.x + v0.w + v1.z + v2.y);
            c.y = 0.25f * (v0.y + v1.x + v1.w + v2.z);
            c.z = 0.25f * (v0.z + v1.y + v2.x + v2.w);
            c.w = 0.f;
            g_cent4[i] = c;
        }
    } else if (blk < PRE_BLKS + CENT_BLKS + CMB_BLKS) {
        // ---- combine: W2u = (W2@Wu1b)/16 ; bc = bu1 + b2@Wu1b ----
        int k = threadIdx.x;
        if (k < 64) {
            int r = blk - (PRE_BLKS + CENT_BLKS);
            if (r < HID) {
                float acc = 0.f;
                #pragma unroll 8
                for (int m = 0; m < HID; m++)
                    acc = fmaf(W2[r * HID + m], Wu1[(HID + m) * HID + k], acc);
                g_W2u[r * HID + k] = acc * (1.0f / 16.0f);
            } else {
                float acc = bu1[k];
                for (int m = 0; m < HID; m++)
                    acc = fmaf(b2[m], Wu1[(HID + m) * HID + k], acc);
                g_bc[k] = acc;
            }
        }
    } else {
        // ---- positions passthrough (float4 copy into out tail) ----
        int idx = (blk - (PRE_BLKS + CENT_BLKS + CMB_BLKS)) * 128 + threadIdx.x;
        if (idx < (N_CELLS * KND * 3) / 4) {
            const float4* s = (const float4*)pos;
            float4* d = ((float4*)out) + (size_t)N_CELLS * HID / 4;
            d[idx] = s[idx];
        }
    }
}

// ============================================================
// K2: pair phase: hsum[i] = sum_d silu(A_i + G_j + geom_ij * w)
// one warp per cell; batch-prefetched gathers; float4 centroids
// ============================================================
__global__ __launch_bounds__(256) void k_pair(const int* __restrict__ nbr,
                                              const float* __restrict__ W1) {
    const unsigned FULL = 0xFFFFFFFFu;
    int i = (blockIdx.x * 256 + threadIdx.x) >> 5;  // exactly 50000 warps
    int lane = threadIdx.x & 31;
    u64 a = *(const u64*)&g_P[(size_t)i * 128 + 2 * lane];
    u64 w = *(const u64*)&W1[128 * 64 + 2 * lane];
    const u64 half2c = pk2(0.5f, 0.5f);
    const float* pbase = g_P + 64 + 2 * lane;

    // per-lane neighbor + geometry (lanes 16-31 mirror 0-15)
    int jd = __ldg(&nbr[(size_t)i * 16 + (lane & 15)]);
    float4 ci = g_cent4[i];            // broadcast
    float4 cj = __ldg(&g_cent4[jd]);   // 1 gather LDG.128 per lane
    float dx = ci.x - cj.x, dy = ci.y - cj.y, dz = ci.z - cj.z;
    float geomv = sqrt_approx(fmaf(dx, dx, fmaf(dy, dy, dz * dz)));

    // batch prefetch: all 16 row-gathers in flight before any math
    int js[16];
    #pragma unroll
    for (int d = 0; d < 16; d++) js[d] = __shfl_sync(FULL, jd, d);
    u64 g[16];
    #pragma unroll
    for (int d = 0; d < 16; d++)
        g[d] = *(const u64*)(pbase + (size_t)js[d] * 128);

    u64 acc = 0ull;
    #pragma unroll
    for (int d = 0; d < 16; d++) {
        float geom = __shfl_sync(FULL, geomv, d);
        u64 pre = fma2(pk2(geom, geom), w, add2(a, g[d]));
        u64 xh = mul2(pre, half2c);
        float xl, xr; upk2(xh, xl, xr);
        u64 t = pk2(tanh_ap(xl), tanh_ap(xr));
        acc = add2(acc, fma2(xh, t, xh));
    }
    *(u64*)&g_hsum[(size_t)i * 64 + 2 * lane] = acc;
}

// ============================================================
// K3: fused update: out = F + silu(F@Wu1a + hsum@W2u + bc) @ Wu2 + bu2
// 64 threads; sS lives in smem only; Wu2 in smem; persistent
// ============================================================
__global__ __launch_bounds__(64) void k_upd(const float* __restrict__ F,
                                            const float* __restrict__ Wu1,
                                            const float* __restrict__ Wu2,
                                            const float* __restrict__ bu2,
                                            float* __restrict__ out) {
    __shared__ __align__(16) float fs[32 * 64];
    __shared__ __align__(16) float hs[32 * 64];
    __shared__ __align__(16) float ss[32 * 64];
    __shared__ __align__(16) u64 w2s[32 * 64];   // pk2(Wu2[2r][k], Wu2[2r+1][k])
    int k = threadIdx.x;
    u64 wa[32], wb[32];
    #pragma unroll
    for (int r = 0; r < 32; r++) {
        wa[r] = pk2(Wu1[(2 * r) * 64 + k],   Wu1[(2 * r + 1) * 64 + k]);
        wb[r] = pk2(g_W2u[(2 * r) * 64 + k], g_W2u[(2 * r + 1) * 64 + k]);
    }
    // stage Wu2 into smem (packed)
    for (int idx = k; idx < 32 * 64; idx += 64) {
        int r = idx >> 6, kk = idx & 63;
        w2s[idx] = pk2(Wu2[(2 * r) * 64 + kk], Wu2[(2 * r + 1) * 64 + kk]);
    }
    float bias = g_bc[k];
    float bias2 = bu2[k];

    for (int t = blockIdx.x; t < NTILES; t += UPD_BLKS) {
        int c0 = t * 32;
        int nc = min(32, N_CELLS - c0);
        {
            const float4* s1 = (const float4*)(F + (size_t)c0 * 64);
            const float4* s2 = (const float4*)(g_hsum + (size_t)c0 * 64);
            float4* d1 = (float4*)fs;
            float4* d2 = (float4*)hs;
            for (int q = k; q < nc * 16; q += 64) { d1[q] = s1[q]; d2[q] = s2[q]; }
        }
        __syncthreads();
        // stage 1: sS into smem
        for (int c = 0; c < nc; c++) {
            u64 a0 = pk2(bias, 0.f), a1 = 0ull;
            const ulonglong2* fp = (const ulonglong2*)&fs[c * 64];
            const ulonglong2* hp = (const ulonglong2*)&hs[c * 64];
            #pragma unroll
            for (int r = 0; r < 16; r++) {
                ulonglong2 qf = fp[r], qh = hp[r];
                a0 = fma2(qf.x, wa[2 * r],     a0);
                a1 = fma2(qf.y, wa[2 * r + 1], a1);
                a0 = fma2(qh.x, wb[2 * r],     a0);
                a1 = fma2(qh.y, wb[2 * r + 1], a1);
            }
            float l0, h0, l1, h1; upk2(a0, l0, h0); upk2(a1, l1, h1);
            float x = (l0 + h0) + (l1 + h1);
            float xh = 0.5f * x;
            ss[c * 64 + k] = fmaf(xh, tanh_ap(xh), xh);
        }
        __syncthreads();
        // stage 2: out = F + sS @ Wu2 + bu2
        for (int c = 0; c < nc; c++) {
            u64 a0 = pk2(bias2, 0.f), a1 = 0ull;
            const ulonglong2* sp = (const ulonglong2*)&ss[c * 64];
            #pragma unroll
            for (int r = 0; r < 16; r++) {
                ulonglong2 q = sp[r];
                a0 = fma2(q.x, w2s[(2 * r) * 64 + k],     a0);
                a1 = fma2(q.y, w2s[(2 * r + 1) * 64 + k], a1);
            }
            float l0, h0, l1, h1; upk2(a0, l0, h0); upk2(a1, l1, h1);
            size_t idx = (size_t)(c0 + c) * 64 + k;
            out[idx] = F[idx] + (l0 + h0) + (l1 + h1);
        }
        __syncthreads();
    }
}

extern "C" void kernel_launch(void* const* d_in, const int* in_sizes, int n_in,
                              void* d_out, int out_size) {
    const float* F   = (const float*)d_in[0];
    const float* pos = (const float*)d_in[1];
    const int*   nbr = (const int*)d_in[2];
    const float* W1  = (const float*)d_in[3];
    const float* b1  = (const float*)d_in[4];
    const float* W2  = (const float*)d_in[5];
    const float* b2  = (const float*)d_in[6];
    const float* Wu1 = (const float*)d_in[7];
    const float* bu1 = (const float*)d_in[8];
    const float* Wu2 = (const float*)d_in[9];
    const float* bu2 = (const float*)d_in[10];
    float* out = (float*)d_out;

    int mega_grid = PRE_BLKS + CENT_BLKS + CMB_BLKS + POS_BLKS;
    k_mega<<<mega_grid, 128>>>(F, W1, b1, pos, W2, b2, Wu1, bu1, out);
    k_pair<<<(N_CELLS * 32) / 256, 256>>>(nbr, W1);
    k_upd<<<UPD_BLKS, 64>>>(F, Wu1, Wu2, bu2, out);
}